// round 8
// baseline (speedup 1.0000x reference)
#include <cuda_runtime.h>
#include <cuda_bf16.h>
#include <cstdint>

// Problem constants (fixed by the dataset)
#define H    256
#define NMAX 8192
#define EMAX 8192
#define KTOT 512            // concatenated K dim: [xi | xj]

// ---------------- scratch (static __device__ — no allocations) ----------------
__device__ uint32_t      g_bits[(size_t)NMAX * (NMAX / 32)];  // 8 MB packed adjacency (lane-local layout)
__device__ __nv_bfloat16 g_Xhi[(size_t)NMAX * H];             // 4 MB bf16 hi of x
__device__ __nv_bfloat16 g_Xlo[(size_t)NMAX * H];             // 4 MB bf16 lo of x
__device__ __nv_bfloat16 g_Wthi[(size_t)H * KTOT];            // 256 KB: Wt[n][k] hi
__device__ __nv_bfloat16 g_Wtlo[(size_t)H * KTOT];            // 256 KB
__device__ float         g_tq[4][EMAX];                       // per-edge relu-dot, col quarters
__device__ float         g_s2[NMAX];                          // s2[n] = x2[n]·vcn
__device__ float         g_vcn[H];
__device__ float         g_vf[H];
__device__ float         g_ws2[H];
__device__ float         g_consts[4];                         // [0]=bcn·ws, [1]=bf·ws+bs, [2]=blin·vcn
__device__ unsigned char g_flag[NMAX];                        // adj row referenced by any edge?

// Bit layout (pack/decode contract):
//   chunk gw covers 2048 floats at adj + gw*2048 (4 chunks per adjacency row).
//   lane L, iter i (0..15) packs float4 at float-offset i*128 + L*4 into nibble i.
//   word = g_bits[gw*64 + L*2 + half], half = i>>3, bit b = (i&7)*4 + component j.
//   decode: node = gw*2048 + half*1024 + (b>>2)*128 + L*4 + (b&3).

// ---------------- helpers ----------------
__device__ __forceinline__ float warp_red(float v) {
#pragma unroll
    for (int o = 16; o; o >>= 1) v += __shfl_xor_sync(0xffffffffu, v, o);
    return v;
}

__device__ __forceinline__ float warp_dot256(const float* __restrict__ row,
                                             const float* __restrict__ vec, int lane) {
    float s = 0.f;
#pragma unroll
    for (int c = 0; c < H; c += 32) s = fmaf(row[c + lane], vec[c + lane], s);
    return warp_red(s);
}

// block-wide sum of one float per thread (256 threads); result valid in thread 0
__device__ __forceinline__ float block_red256(float v, float* sm8) {
    int lane = threadIdx.x & 31, w = threadIdx.x >> 5;
    v = warp_red(v);
    if (!lane) sm8[w] = v;
    __syncthreads();
    float t = 0.f;
    if (w == 0) {
        t = (lane < 8) ? sm8[lane] : 0.f;
        t += __shfl_xor_sync(0xffffffffu, t, 1);
        t += __shfl_xor_sync(0xffffffffu, t, 2);
        t += __shfl_xor_sync(0xffffffffu, t, 4);
    }
    return t;
}

__device__ __forceinline__ void mma16816(float c[4], const uint32_t a[4],
                                         uint32_t b0, uint32_t b1) {
    asm volatile(
        "mma.sync.aligned.m16n8k16.row.col.f32.bf16.bf16.f32 "
        "{%0,%1,%2,%3}, {%4,%5,%6,%7}, {%8,%9}, {%0,%1,%2,%3};"
        : "+f"(c[0]), "+f"(c[1]), "+f"(c[2]), "+f"(c[3])
        : "r"(a[0]), "r"(a[1]), "r"(a[2]), "r"(a[3]), "r"(b0), "r"(b1));
}

__device__ __forceinline__ void ldsm4(uint32_t r[4], uint32_t addr) {
    asm volatile("ldmatrix.sync.aligned.m8n8.x4.shared.b16 {%0,%1,%2,%3}, [%4];"
        : "=r"(r[0]), "=r"(r[1]), "=r"(r[2]), "=r"(r[3]) : "r"(addr));
}

// ---------------- combo head kernel: prep-x ∥ prep-W ∥ flag-zero ∥ k0a ----------------
__global__ void __launch_bounds__(256) combo_kernel(const float* __restrict__ x,
                                                    const float* __restrict__ Wi,
                                                    const float* __restrict__ Wj,
                                                    const float* __restrict__ Wcn,
                                                    const float* __restrict__ Wf,
                                                    const float* __restrict__ ws) {
    __shared__ float sm8[8];
    int bid = blockIdx.x;
    int tid = threadIdx.x;
    const int XB = (NMAX * H) / 1024;          // 2048 blocks: x split
    if (bid < XB) {
        int gid = bid * 256 + tid;
        float4 v = ((const float4*)x)[gid];
        __nv_bfloat16 hx = __float2bfloat16(v.x), hy = __float2bfloat16(v.y);
        __nv_bfloat16 hz = __float2bfloat16(v.z), hw = __float2bfloat16(v.w);
        __nv_bfloat16 lx = __float2bfloat16(v.x - __bfloat162float(hx));
        __nv_bfloat16 ly = __float2bfloat16(v.y - __bfloat162float(hy));
        __nv_bfloat16 lz = __float2bfloat16(v.z - __bfloat162float(hz));
        __nv_bfloat16 lw = __float2bfloat16(v.w - __bfloat162float(hw));
        ((__nv_bfloat162*)g_Xhi)[gid * 2 + 0] = __nv_bfloat162(hx, hy);
        ((__nv_bfloat162*)g_Xhi)[gid * 2 + 1] = __nv_bfloat162(hz, hw);
        ((__nv_bfloat162*)g_Xlo)[gid * 2 + 0] = __nv_bfloat162(lx, ly);
        ((__nv_bfloat162*)g_Xlo)[gid * 2 + 1] = __nv_bfloat162(lz, lw);
    } else if (bid < XB + H) {                 // 256 blocks: W transpose+split
        int n = bid - XB;
        for (int k = tid; k < KTOT; k += 256) {
            float w = (k < H) ? Wi[(size_t)k * H + n] : Wj[(size_t)(k - H) * H + n];
            __nv_bfloat16 hi = __float2bfloat16(w);
            __nv_bfloat16 lo = __float2bfloat16(w - __bfloat162float(hi));
            g_Wthi[(size_t)n * KTOT + k] = hi;
            g_Wtlo[(size_t)n * KTOT + k] = lo;
        }
    } else if (bid < XB + H + 32) {            // 32 blocks: flag zero
        g_flag[(bid - XB - H) * 256 + tid] = 0;
    } else {                                    // 512 blocks: k0a rows
        int r = bid - XB - H - 32;              // 0..511
        const float* W = (r < H) ? (Wcn + (size_t)r * H) : (Wf + (size_t)(r - H) * H);
        float d = block_red256(W[tid] * ws[tid], sm8);
        if (tid == 0) {
            if (r < H) g_vcn[r] = d;
            else       g_vf[r - H] = d;
        }
    }
}

// ---------------- k0b + flagset: ws2/consts + edge-endpoint flags ----------------
__global__ void __launch_bounds__(256) k0b_kernel(const float* __restrict__ Wlin,
                                                  const float* __restrict__ blin,
                                                  const float* __restrict__ bcn,
                                                  const float* __restrict__ bf,
                                                  const float* __restrict__ ws,
                                                  const float* __restrict__ bs,
                                                  const int* __restrict__ tei, int twoE) {
    __shared__ float sm8[8];
    int b = blockIdx.x;
    int tid = threadIdx.x;
    if (b < H) {
        float d = block_red256(Wlin[(size_t)b * H + tid] * g_vcn[tid], sm8);
        if (tid == 0) g_ws2[b] = g_vcn[b] + d;
    } else if (b == H) {
        float d = block_red256(blin[tid] * g_vcn[tid], sm8);
        if (tid == 0) g_consts[2] = d;
    } else if (b == H + 1) {
        float d = block_red256(bcn[tid] * ws[tid], sm8);
        if (tid == 0) g_consts[0] = d;
    } else if (b == H + 2) {
        float d = block_red256(bf[tid] * ws[tid], sm8);
        if (tid == 0) g_consts[1] = d + bs[0];
    } else {
        int gid = (b - H - 3) * 256 + tid;
        if (gid < twoE) g_flag[tei[gid]] = 1;
    }
}

// ---------------- pack: lane-local, shfl-free, two 8-load batches (reg-lean) ----------------
__device__ __forceinline__ void pack_warp(const float* __restrict__ adj,
                                          size_t gw, int lane) {
    if (!g_flag[gw >> 2]) return;                 // adj row never referenced
    const float4* base = (const float4*)(adj + gw * 2048);
    uint32_t w[2];
#pragma unroll
    for (int b = 0; b < 2; b++) {
        float4 v[8];
#pragma unroll
        for (int i = 0; i < 8; i++)
            v[i] = __ldcs(base + (size_t)(b * 8 + i) * 32 + lane);
        uint32_t acc = 0;
#pragma unroll
        for (int i = 0; i < 8; i++) {
            uint32_t nib = (uint32_t)(v[i].x != 0.f)
                         | ((uint32_t)(v[i].y != 0.f) << 1)
                         | ((uint32_t)(v[i].z != 0.f) << 2)
                         | ((uint32_t)(v[i].w != 0.f) << 3);
            acc |= nib << (i * 4);
        }
        w[b] = acc;
    }
    ((uint2*)(g_bits + gw * 64))[lane] = make_uint2(w[0], w[1]);
}

// ---------------- tensor-core edge GEMM body: 64 edges x 64 cols, K=512 ----------------
// split-bf16 3-pass, ldmatrix fragments, acc[4][4]=16 regs (fits 64-reg budget).
#define ROWPAD 12
__device__ __forceinline__ void gemm_block(int h, const int* __restrict__ tei, int E,
                                           const float* __restrict__ bi,
                                           const float* __restrict__ bj,
                                           uint32_t* smem) {
    uint32_t* AsHi = smem;                   // 64*12
    uint32_t* AsLo = smem + 768;
    uint32_t* BsHi = smem + 1536;            // 64*12
    uint32_t* BsLo = smem + 2304;
    float*    tsum = (float*)(smem + 3072);  // [2][64]
    int*      eidx = (int*)(smem + 3200);    // [64 src][64 dst]

    int nq = h & 3;                          // column quarter (64 cols)
    int eb = h >> 2;                         // edge tile
    int n0 = nq * 64;
    int ebase = eb * 64;

    int tid = threadIdx.x;
    int lane = tid & 31, wid = tid >> 5;
    int wm = wid & 3, wn = wid >> 2;         // 4 m-groups x 2 n-groups (32 cols each)

    if (tid < 64) {
        eidx[tid]      = tei[ebase + tid];
        eidx[64 + tid] = tei[E + ebase + tid];
    }
    __syncthreads();

    int arow = tid >> 2, aq = tid & 3;       // A smem-fill mapping
    int brow = tid >> 2, bq = tid & 3;       // B smem-fill: 64 rows x {hi0,hi1,lo0,lo1}

    uint32_t asHiB = (uint32_t)__cvta_generic_to_shared(AsHi);
    uint32_t asLoB = (uint32_t)__cvta_generic_to_shared(AsLo);
    uint32_t bsHiB = (uint32_t)__cvta_generic_to_shared(BsHi);
    uint32_t bsLoB = (uint32_t)__cvta_generic_to_shared(BsLo);
    uint32_t aoff = (uint32_t)((wm * 16 + (lane & 15)) * 48 + (lane >> 4) * 16);
    uint32_t boff0 = (uint32_t)((wn * 32 + (lane & 15)) * 48 + (lane >> 4) * 16);
    uint32_t boff1 = (uint32_t)((wn * 32 + 16 + (lane & 15)) * 48 + (lane >> 4) * 16);

    float acc[4][4];
#pragma unroll
    for (int j = 0; j < 4; j++)
#pragma unroll
        for (int q = 0; q < 4; q++) acc[j][q] = 0.f;

    for (int ks = 0; ks < KTOT / 16; ks++) {
        int k0 = ks * 16;
        {
            int node = eidx[(k0 < H ? 0 : 64) + arow];
            int gc = (k0 & (H - 1)) + aq * 4;
            uint2 vh = *(const uint2*)(g_Xhi + (size_t)node * H + gc);
            uint2 vl = *(const uint2*)(g_Xlo + (size_t)node * H + gc);
            AsHi[arow * ROWPAD + aq * 2 + 0] = vh.x;
            AsHi[arow * ROWPAD + aq * 2 + 1] = vh.y;
            AsLo[arow * ROWPAD + aq * 2 + 0] = vl.x;
            AsLo[arow * ROWPAD + aq * 2 + 1] = vl.y;
        }
        {
            size_t goff = (size_t)(n0 + brow) * KTOT + k0 + (bq & 1) * 8;
            if (bq < 2)
                *(uint4*)&BsHi[brow * ROWPAD + (bq & 1) * 4] = *(const uint4*)(g_Wthi + goff);
            else
                *(uint4*)&BsLo[brow * ROWPAD + (bq & 1) * 4] = *(const uint4*)(g_Wtlo + goff);
        }
        __syncthreads();

        uint32_t ah[4], al[4];
        ldsm4(ah, asHiB + aoff);
        ldsm4(al, asLoB + aoff);
        {
            uint32_t bhf[4], blf[4];
            ldsm4(bhf, bsHiB + boff0);
            ldsm4(blf, bsLoB + boff0);
            mma16816(acc[0], ah, bhf[0], bhf[2]);
            mma16816(acc[0], ah, blf[0], blf[2]);
            mma16816(acc[0], al, bhf[0], bhf[2]);
            mma16816(acc[1], ah, bhf[1], bhf[3]);
            mma16816(acc[1], ah, blf[1], blf[3]);
            mma16816(acc[1], al, bhf[1], bhf[3]);
        }
        {
            uint32_t bhf[4], blf[4];
            ldsm4(bhf, bsHiB + boff1);
            ldsm4(blf, bsLoB + boff1);
            mma16816(acc[2], ah, bhf[0], bhf[2]);
            mma16816(acc[2], ah, blf[0], blf[2]);
            mma16816(acc[2], al, bhf[0], bhf[2]);
            mma16816(acc[3], ah, bhf[1], bhf[3]);
            mma16816(acc[3], ah, blf[1], blf[3]);
            mma16816(acc[3], al, bhf[1], bhf[3]);
        }
        __syncthreads();
    }

    float tp0 = 0.f, tp1 = 0.f;
#pragma unroll
    for (int j = 0; j < 4; j++) {
        int col = n0 + wn * 32 + j * 8 + (lane & 3) * 2;
        float b0 = bi[col] + bj[col];
        float b1 = bi[col + 1] + bj[col + 1];
        float v0 = g_vf[col], v1 = g_vf[col + 1];
        tp0 += fmaxf(acc[j][0] + b0, 0.f) * v0 + fmaxf(acc[j][1] + b1, 0.f) * v1;
        tp1 += fmaxf(acc[j][2] + b0, 0.f) * v0 + fmaxf(acc[j][3] + b1, 0.f) * v1;
    }
    tp0 += __shfl_xor_sync(0xffffffffu, tp0, 1);
    tp0 += __shfl_xor_sync(0xffffffffu, tp0, 2);
    tp1 += __shfl_xor_sync(0xffffffffu, tp1, 1);
    tp1 += __shfl_xor_sync(0xffffffffu, tp1, 2);
    if ((lane & 3) == 0) {
        int r = wm * 16 + (lane >> 2);
        tsum[wn * 64 + r] = tp0;
        tsum[wn * 64 + r + 8] = tp1;
    }
    __syncthreads();
    if (tid < 64) g_tq[nq][ebase + tid] = tsum[tid] + tsum[64 + tid];
}

// ---------------- fused kernel: pack ∪ tensor-GEMM ∪ s2 (4 blocks/SM) ----------------
__global__ void __launch_bounds__(256, 4) fused_kernel(const float* __restrict__ x,
                                                       const float* __restrict__ adj,
                                                       const int* __restrict__ tei,
                                                       const float* __restrict__ bi,
                                                       const float* __restrict__ bj,
                                                       int N, int E) {
    __shared__ uint32_t smem[3328];   // 13 KB (gemm role only)

    const int nbGemm = (E / 64) * 4;  // 512
    const int nbS2   = N / 8;         // 1024
    int bid = blockIdx.x;
    int warp = threadIdx.x >> 5;
    int lane = threadIdx.x & 31;

    if (bid < 2 * nbGemm) {
        int half = bid >> 1;
        if ((bid & 1) == 0) {
            gemm_block(half, tei, E, bi, bj, smem);
        } else {
            pack_warp(adj, (size_t)half * 8 + warp, lane);
        }
    } else if (bid < 2 * nbGemm + nbS2) {
        int node = (bid - 2 * nbGemm) * 8 + warp;
        if (node < N) {
            float d = warp_dot256(x + (size_t)node * H, g_ws2, lane);
            if (!lane) g_s2[node] = d + g_consts[2];
        }
    } else {
        int pb = nbGemm + (bid - 2 * nbGemm - nbS2);
        pack_warp(adj, (size_t)pb * 8 + warp, lane);
    }
}

// ---------------- final edge kernel (decodes the lane-local bit layout) ----------------
__global__ void __launch_bounds__(256) edge_kernel(const int* __restrict__ tei, int E, int nwords,
                                                   const float* __restrict__ beta_p,
                                                   const int* __restrict__ boolen_p,
                                                   float* __restrict__ out) {
    int gw = (blockIdx.x * blockDim.x + threadIdx.x) >> 5;
    int lane = threadIdx.x & 31;
    if (gw >= E) return;

    int src = tei[gw];
    int dst = tei[E + gw];

    const uint32_t* bsrc = g_bits + (size_t)src * nwords;
    const uint32_t* bdst = g_bits + (size_t)dst * nwords;

    float s = 0.f;
    int rounds = nwords >> 5;          // 8 for N=8192
    for (int rb = 0; rb < rounds; rb += 8) {
        uint32_t aw[8], bw[8];
#pragma unroll
        for (int i = 0; i < 8; i++) {
            int w = lane + ((rb + i) << 5);
            aw[i] = bsrc[w];
            bw[i] = bdst[w];
        }
#pragma unroll
        for (int i = 0; i < 8; i++) {
            int w = lane + ((rb + i) << 5);
            uint32_t a = aw[i] & bw[i];
            if (a) {
                // decode: chunk = w>>6, L = (w&63)>>1, half = w&1
                int nb = ((w >> 6) << 11) + ((w & 1) << 10) + ((w >> 1) & 31) * 4;
                do {
                    int b = __ffs(a) - 1;
                    a &= a - 1;
                    s += g_s2[nb + ((b >> 2) << 7) + (b & 3)];
                } while (a);
            }
        }
    }
    float S = warp_red(s);

    if (!lane) {
        float beta = beta_p[0];
        float u = g_tq[0][gw] + g_tq[1][gw] + g_tq[2][gw] + g_tq[3][gw]
                + beta * (S + g_consts[0]) + g_consts[1];
        bool pos = boolen_p ? (boolen_p[0] != 0) : true;
        float v = pos ? u : -u;
        out[gw] = fmaxf(-v, 0.f) + log1pf(expf(-fabsf(v)));  // softplus(-v)
    }
}

// ---------------- launch ----------------
extern "C" void kernel_launch(void* const* d_in, const int* in_sizes, int n_in,
                              void* d_out, int out_size) {
    const float* x    = (const float*)d_in[0];
    const float* adj  = (const float*)d_in[1];
    const int*   tei  = (const int*)d_in[2];
    const float* Wlin = (const float*)d_in[3];
    const float* blin = (const float*)d_in[4];
    const float* Wcn  = (const float*)d_in[5];
    const float* bcn  = (const float*)d_in[6];
    const float* Wi   = (const float*)d_in[7];
    const float* bi   = (const float*)d_in[8];
    const float* Wj   = (const float*)d_in[9];
    const float* bj   = (const float*)d_in[10];
    const float* Wf   = (const float*)d_in[11];
    const float* bf   = (const float*)d_in[12];
    const float* ws   = (const float*)d_in[13];
    const float* bs   = (const float*)d_in[14];
    const float* beta = (const float*)d_in[15];
    const int* boolen = (n_in > 16) ? (const int*)d_in[16] : nullptr;
    float* out = (float*)d_out;

    const int N = in_sizes[0] / H;   // 8192 nodes
    const int E = in_sizes[2] / 2;   // 8192 edges
    const int nwords = N / 32;       // 256 words per adjacency row

    // 1) combo head: x split ∥ W split ∥ flag zero ∥ k0a
    combo_kernel<<<(NMAX * H) / 1024 + H + 32 + 2 * H, 256>>>(x, Wi, Wj, Wcn, Wf, ws);
    // 2) k0b (needs vcn) + flagset (needs zeroed flags) in one launch
    k0b_kernel<<<H + 3 + (2 * E + 255) / 256, 256>>>(Wlin, blin, bcn, bf, ws, bs, tei, 2 * E);
    // 3) fused: shfl-free pack (DRAM) + tensor GEMM + s2 GEMV, 4 blocks/SM
    {
        int nbGemm = (E / 64) * 4;                        // 512
        int nbS2   = N / 8;                               // 1024
        int nbPack = (int)((long long)N * N / 2048 / 8);  // 4096
        int total = nbGemm + nbS2 + nbPack;               // 5632
        fused_kernel<<<total, 256>>>(x, adj, tei, bi, bj, N, E);
    }
    // 4) per-edge: CN bit-AND gather + combine + softplus
    edge_kernel<<<(E + 7) / 8, 256>>>(tei, E, nwords, beta, boolen, out);
}

// round 9
// speedup vs baseline: 1.0266x; 1.0266x over previous
#include <cuda_runtime.h>
#include <cuda_bf16.h>
#include <cstdint>

// Problem constants (fixed by the dataset)
#define H    256
#define NMAX 8192
#define EMAX 8192
#define KTOT 512            // concatenated K dim: [xi | xj]

// ---------------- scratch (static __device__ — no allocations) ----------------
__device__ uint32_t      g_bits[(size_t)NMAX * (NMAX / 32)];  // 8 MB packed adjacency (lane-local layout)
__device__ __nv_bfloat16 g_Xhi[(size_t)NMAX * H];             // 4 MB bf16 hi of x
__device__ __nv_bfloat16 g_Xlo[(size_t)NMAX * H];             // 4 MB bf16 lo of x
__device__ __nv_bfloat16 g_Wthi[(size_t)H * KTOT];            // 256 KB: Wt[n][k] hi
__device__ __nv_bfloat16 g_Wtlo[(size_t)H * KTOT];            // 256 KB
__device__ float         g_t0[EMAX];                          // per-edge relu-dot, cols 0-127
__device__ float         g_t1[EMAX];                          // per-edge relu-dot, cols 128-255
__device__ float         g_s2[NMAX];                          // s2[n] = x2[n]·vcn
__device__ float         g_vcn[H];
__device__ float         g_vf[H];
__device__ float         g_ws2[H];
__device__ float         g_consts[4];                         // [0]=bcn·ws, [1]=bf·ws+bs, [2]=blin·vcn
__device__ unsigned char g_flag[NMAX];                        // adj row referenced by any edge?

// Bit layout (pack/decode contract):
//   chunk gw covers 2048 floats at adj + gw*2048 (4 chunks per adjacency row).
//   lane L, iter i (0..15) packs float4 at float-offset i*128 + L*4 into nibble i.
//   word = g_bits[gw*64 + L*2 + half], half = i>>3, bit b = (i&7)*4 + component j.
//   decode: node = gw*2048 + half*1024 + (b>>2)*128 + L*4 + (b&3).

// ---------------- helpers ----------------
__device__ __forceinline__ float warp_red(float v) {
#pragma unroll
    for (int o = 16; o; o >>= 1) v += __shfl_xor_sync(0xffffffffu, v, o);
    return v;
}

__device__ __forceinline__ float warp_dot256(const float* __restrict__ row,
                                             const float* __restrict__ vec, int lane) {
    float s = 0.f;
#pragma unroll
    for (int c = 0; c < H; c += 32) s = fmaf(row[c + lane], vec[c + lane], s);
    return warp_red(s);
}

// block-wide sum of one float per thread (256 threads); result valid in thread 0
__device__ __forceinline__ float block_red256(float v, float* sm8) {
    int lane = threadIdx.x & 31, w = threadIdx.x >> 5;
    v = warp_red(v);
    if (!lane) sm8[w] = v;
    __syncthreads();
    float t = 0.f;
    if (w == 0) {
        t = (lane < 8) ? sm8[lane] : 0.f;
        t += __shfl_xor_sync(0xffffffffu, t, 1);
        t += __shfl_xor_sync(0xffffffffu, t, 2);
        t += __shfl_xor_sync(0xffffffffu, t, 4);
    }
    return t;
}

__device__ __forceinline__ void mma16816(float c[4], const uint32_t a[4],
                                         uint32_t b0, uint32_t b1) {
    asm volatile(
        "mma.sync.aligned.m16n8k16.row.col.f32.bf16.bf16.f32 "
        "{%0,%1,%2,%3}, {%4,%5,%6,%7}, {%8,%9}, {%0,%1,%2,%3};"
        : "+f"(c[0]), "+f"(c[1]), "+f"(c[2]), "+f"(c[3])
        : "r"(a[0]), "r"(a[1]), "r"(a[2]), "r"(a[3]), "r"(b0), "r"(b1));
}

__device__ __forceinline__ void ldsm4(uint32_t r[4], uint32_t addr) {
    asm volatile("ldmatrix.sync.aligned.m8n8.x4.shared.b16 {%0,%1,%2,%3}, [%4];"
        : "=r"(r[0]), "=r"(r[1]), "=r"(r[2]), "=r"(r[3]) : "r"(addr));
}

__device__ __forceinline__ void mbar_wait(uint32_t mbar, uint32_t parity) {
    asm volatile(
        "{\n\t.reg .pred P1;\n\t"
        "WAIT_LOOP_%=:\n\t"
        "mbarrier.try_wait.parity.acquire.cta.shared::cta.b64 P1, [%0], %1;\n\t"
        "@P1 bra WAIT_DONE_%=;\n\t"
        "bra WAIT_LOOP_%=;\n\t"
        "WAIT_DONE_%=:\n\t}"
        :: "r"(mbar), "r"(parity) : "memory");
}

// ---------------- combo head kernel: prep-x ∥ prep-W ∥ flag-zero ∥ k0a ----------------
__global__ void __launch_bounds__(256) combo_kernel(const float* __restrict__ x,
                                                    const float* __restrict__ Wi,
                                                    const float* __restrict__ Wj,
                                                    const float* __restrict__ Wcn,
                                                    const float* __restrict__ Wf,
                                                    const float* __restrict__ ws) {
    __shared__ float sm8[8];
    int bid = blockIdx.x;
    int tid = threadIdx.x;
    const int XB = (NMAX * H) / 1024;          // 2048 blocks: x split
    if (bid < XB) {
        int gid = bid * 256 + tid;
        float4 v = ((const float4*)x)[gid];
        __nv_bfloat16 hx = __float2bfloat16(v.x), hy = __float2bfloat16(v.y);
        __nv_bfloat16 hz = __float2bfloat16(v.z), hw = __float2bfloat16(v.w);
        __nv_bfloat16 lx = __float2bfloat16(v.x - __bfloat162float(hx));
        __nv_bfloat16 ly = __float2bfloat16(v.y - __bfloat162float(hy));
        __nv_bfloat16 lz = __float2bfloat16(v.z - __bfloat162float(hz));
        __nv_bfloat16 lw = __float2bfloat16(v.w - __bfloat162float(hw));
        ((__nv_bfloat162*)g_Xhi)[gid * 2 + 0] = __nv_bfloat162(hx, hy);
        ((__nv_bfloat162*)g_Xhi)[gid * 2 + 1] = __nv_bfloat162(hz, hw);
        ((__nv_bfloat162*)g_Xlo)[gid * 2 + 0] = __nv_bfloat162(lx, ly);
        ((__nv_bfloat162*)g_Xlo)[gid * 2 + 1] = __nv_bfloat162(lz, lw);
    } else if (bid < XB + H) {                 // 256 blocks: W transpose+split
        int n = bid - XB;
        for (int k = tid; k < KTOT; k += 256) {
            float w = (k < H) ? Wi[(size_t)k * H + n] : Wj[(size_t)(k - H) * H + n];
            __nv_bfloat16 hi = __float2bfloat16(w);
            __nv_bfloat16 lo = __float2bfloat16(w - __bfloat162float(hi));
            g_Wthi[(size_t)n * KTOT + k] = hi;
            g_Wtlo[(size_t)n * KTOT + k] = lo;
        }
    } else if (bid < XB + H + 32) {            // 32 blocks: flag zero
        g_flag[(bid - XB - H) * 256 + tid] = 0;
    } else {                                    // 512 blocks: k0a rows
        int r = bid - XB - H - 32;              // 0..511
        const float* W = (r < H) ? (Wcn + (size_t)r * H) : (Wf + (size_t)(r - H) * H);
        float d = block_red256(W[tid] * ws[tid], sm8);
        if (tid == 0) {
            if (r < H) g_vcn[r] = d;
            else       g_vf[r - H] = d;
        }
    }
}

// ---------------- k0b + flagset: ws2/consts + edge-endpoint flags ----------------
__global__ void __launch_bounds__(256) k0b_kernel(const float* __restrict__ Wlin,
                                                  const float* __restrict__ blin,
                                                  const float* __restrict__ bcn,
                                                  const float* __restrict__ bf,
                                                  const float* __restrict__ ws,
                                                  const float* __restrict__ bs,
                                                  const int* __restrict__ tei, int twoE) {
    __shared__ float sm8[8];
    int b = blockIdx.x;
    int tid = threadIdx.x;
    if (b < H) {
        float d = block_red256(Wlin[(size_t)b * H + tid] * g_vcn[tid], sm8);
        if (tid == 0) g_ws2[b] = g_vcn[b] + d;
    } else if (b == H) {
        float d = block_red256(blin[tid] * g_vcn[tid], sm8);
        if (tid == 0) g_consts[2] = d;
    } else if (b == H + 1) {
        float d = block_red256(bcn[tid] * ws[tid], sm8);
        if (tid == 0) g_consts[0] = d;
    } else if (b == H + 2) {
        float d = block_red256(bf[tid] * ws[tid], sm8);
        if (tid == 0) g_consts[1] = d + bs[0];
    } else {
        int gid = (b - H - 3) * 256 + tid;
        if (gid < twoE) g_flag[tei[gid]] = 1;
    }
}

// ---------------- pack: TMA bulk-copy staged, lane-local nibble pack ----------------
// Per warp: 8 KB chunk staged via cp.async.bulk in 4 stages of 2 KB, 2-deep
// double buffer with a private mbarrier pair. No LDG, no L1tex wavefronts,
// no register front-batch. Consumption is LDS.128 + pure ALU.
__device__ __forceinline__ void pack_warp_tma(const float* __restrict__ adj,
                                              size_t gw, int lane,
                                              uint32_t stage_b, uint32_t mbar_b) {
    if (!g_flag[gw >> 2]) return;                 // adj row never referenced
    const char* src = (const char*)(adj + gw * 2048);
    if (lane == 0) {
        asm volatile("mbarrier.init.shared.b64 [%0], 1;" :: "r"(mbar_b) : "memory");
        asm volatile("mbarrier.init.shared.b64 [%0], 1;" :: "r"(mbar_b + 8) : "memory");
        asm volatile("fence.proxy.async.shared::cta;" ::: "memory");
#pragma unroll
        for (int p = 0; p < 2; p++) {
            asm volatile("mbarrier.arrive.expect_tx.shared.b64 _, [%0], %1;"
                :: "r"(mbar_b + p * 8), "r"(2048) : "memory");
            asm volatile("cp.async.bulk.shared::cluster.global.mbarrier::complete_tx::bytes [%0], [%1], %2, [%3];"
                :: "r"(stage_b + p * 2048), "l"(src + (size_t)p * 2048), "r"(2048),
                   "r"(mbar_b + p * 8) : "memory");
        }
    }
    __syncwarp();
    uint32_t w0 = 0, w1 = 0;
#pragma unroll
    for (int s = 0; s < 4; s++) {
        uint32_t mb = mbar_b + (s & 1) * 8;
        mbar_wait(mb, (s >> 1) & 1);
        uint32_t base = stage_b + (s & 1) * 2048 + lane * 16;
#pragma unroll
        for (int q = 0; q < 4; q++) {
            float vx, vy, vz, vw;
            asm volatile("ld.shared.v4.f32 {%0,%1,%2,%3}, [%4];"
                : "=f"(vx), "=f"(vy), "=f"(vz), "=f"(vw) : "r"(base + q * 512));
            uint32_t nib = (uint32_t)(vx != 0.f)
                         | ((uint32_t)(vy != 0.f) << 1)
                         | ((uint32_t)(vz != 0.f) << 2)
                         | ((uint32_t)(vw != 0.f) << 3);
            int i = s * 4 + q;
            if (i < 8) w0 |= nib << (i * 4);
            else       w1 |= nib << ((i - 8) * 4);
        }
        __syncwarp();
        if (s < 2 && lane == 0) {
            asm volatile("mbarrier.arrive.expect_tx.shared.b64 _, [%0], %1;"
                :: "r"(mb), "r"(2048) : "memory");
            asm volatile("cp.async.bulk.shared::cluster.global.mbarrier::complete_tx::bytes [%0], [%1], %2, [%3];"
                :: "r"(stage_b + (s & 1) * 2048), "l"(src + (size_t)(s + 2) * 2048), "r"(2048),
                   "r"(mb) : "memory");
        }
    }
    ((uint2*)(g_bits + gw * 64))[lane] = make_uint2(w0, w1);
}

// ---------------- tensor-core edge GEMM body: 64 edges x 128 cols, K=512 (R7) ----------------
#define ROWPAD 12
__device__ __forceinline__ void gemm_block(int h, const int* __restrict__ tei, int E,
                                           const float* __restrict__ bi,
                                           const float* __restrict__ bj,
                                           uint32_t* smem) {
    uint32_t* AsHi = smem;                   // 64*12
    uint32_t* AsLo = smem + 768;
    uint32_t* BsHi = smem + 1536;            // 128*12
    uint32_t* BsLo = smem + 3072;
    float*    tsum = (float*)(smem + 4608);  // [2][64]
    int*      eidx = (int*)(smem + 4736);    // [64 src][64 dst]

    int np = h & 1;                          // column half
    int eb = h >> 1;                         // edge tile
    int ebase = eb * 64;

    int tid = threadIdx.x;
    int lane = tid & 31, wid = tid >> 5;
    int wm = wid & 3, wn = wid >> 2;

    if (tid < 64) {
        eidx[tid]      = tei[ebase + tid];
        eidx[64 + tid] = tei[E + ebase + tid];
    }
    __syncthreads();

    int arow = tid >> 2, aq = tid & 3;
    int brow = tid >> 1, bh2 = tid & 1;

    uint32_t asHiB = (uint32_t)__cvta_generic_to_shared(AsHi);
    uint32_t asLoB = (uint32_t)__cvta_generic_to_shared(AsLo);
    uint32_t bsHiB = (uint32_t)__cvta_generic_to_shared(BsHi);
    uint32_t bsLoB = (uint32_t)__cvta_generic_to_shared(BsLo);
    uint32_t aoff = (uint32_t)((wm * 16 + (lane & 15)) * 48 + (lane >> 4) * 16);
    uint32_t boff[4];
#pragma unroll
    for (int jj = 0; jj < 4; jj++)
        boff[jj] = (uint32_t)((wn * 64 + jj * 16 + (lane & 15)) * 48 + (lane >> 4) * 16);

    float acc[8][4];
#pragma unroll
    for (int j = 0; j < 8; j++)
#pragma unroll
        for (int q = 0; q < 4; q++) acc[j][q] = 0.f;

    for (int ks = 0; ks < KTOT / 16; ks++) {
        int k0 = ks * 16;
        {
            int node = eidx[(k0 < H ? 0 : 64) + arow];
            int gc = (k0 & (H - 1)) + aq * 4;
            uint2 vh = *(const uint2*)(g_Xhi + (size_t)node * H + gc);
            uint2 vl = *(const uint2*)(g_Xlo + (size_t)node * H + gc);
            AsHi[arow * ROWPAD + aq * 2 + 0] = vh.x;
            AsHi[arow * ROWPAD + aq * 2 + 1] = vh.y;
            AsLo[arow * ROWPAD + aq * 2 + 0] = vl.x;
            AsLo[arow * ROWPAD + aq * 2 + 1] = vl.y;
        }
        {
            size_t goff = (size_t)(np * 128 + brow) * KTOT + k0 + bh2 * 8;
            *(uint4*)&BsHi[brow * ROWPAD + bh2 * 4] = *(const uint4*)(g_Wthi + goff);
            *(uint4*)&BsLo[brow * ROWPAD + bh2 * 4] = *(const uint4*)(g_Wtlo + goff);
        }
        __syncthreads();

        uint32_t ah[4], al[4];
        ldsm4(ah, asHiB + aoff);
        ldsm4(al, asLoB + aoff);
#pragma unroll
        for (int jj = 0; jj < 4; jj++) {
            uint32_t bhf[4], blf[4];
            ldsm4(bhf, bsHiB + boff[jj]);
            ldsm4(blf, bsLoB + boff[jj]);
            mma16816(acc[2 * jj],     ah, bhf[0], bhf[2]);
            mma16816(acc[2 * jj],     ah, blf[0], blf[2]);
            mma16816(acc[2 * jj],     al, bhf[0], bhf[2]);
            mma16816(acc[2 * jj + 1], ah, bhf[1], bhf[3]);
            mma16816(acc[2 * jj + 1], ah, blf[1], blf[3]);
            mma16816(acc[2 * jj + 1], al, bhf[1], bhf[3]);
        }
        __syncthreads();
    }

    float tp0 = 0.f, tp1 = 0.f;
#pragma unroll
    for (int j = 0; j < 8; j++) {
        int col = np * 128 + wn * 64 + j * 8 + (lane & 3) * 2;
        float b0 = bi[col] + bj[col];
        float b1 = bi[col + 1] + bj[col + 1];
        float v0 = g_vf[col], v1 = g_vf[col + 1];
        tp0 += fmaxf(acc[j][0] + b0, 0.f) * v0 + fmaxf(acc[j][1] + b1, 0.f) * v1;
        tp1 += fmaxf(acc[j][2] + b0, 0.f) * v0 + fmaxf(acc[j][3] + b1, 0.f) * v1;
    }
    tp0 += __shfl_xor_sync(0xffffffffu, tp0, 1);
    tp0 += __shfl_xor_sync(0xffffffffu, tp0, 2);
    tp1 += __shfl_xor_sync(0xffffffffu, tp1, 1);
    tp1 += __shfl_xor_sync(0xffffffffu, tp1, 2);
    if ((lane & 3) == 0) {
        int r = wm * 16 + (lane >> 2);
        tsum[wn * 64 + r] = tp0;
        tsum[wn * 64 + r + 8] = tp1;
    }
    __syncthreads();
    if (tid < 64) {
        float v = tsum[tid] + tsum[64 + tid];
        if (np == 0) g_t0[ebase + tid] = v;
        else         g_t1[ebase + tid] = v;
    }
}

// ---------------- fused kernel: TMA-pack ∪ tensor-GEMM ∪ s2 ----------------
// smem union: GEMM role uses words [0,4864); pack role uses [0,8192) as 8x4KB
// staging + [8192,8224) as per-warp mbarrier pairs. Roles are block-exclusive.
__global__ void __launch_bounds__(256, 3) fused_kernel(const float* __restrict__ x,
                                                       const float* __restrict__ adj,
                                                       const int* __restrict__ tei,
                                                       const float* __restrict__ bi,
                                                       const float* __restrict__ bj,
                                                       int N, int E) {
    __shared__ __align__(128) uint32_t smem[8224];   // 32.9 KB

    const int nbGemm = (E / 64) * 2;  // 256
    const int nbS2   = N / 8;         // 1024
    int bid = blockIdx.x;
    int warp = threadIdx.x >> 5;
    int lane = threadIdx.x & 31;

    uint32_t smem_b = (uint32_t)__cvta_generic_to_shared(smem);
    uint32_t stage_b = smem_b + warp * 4096;
    uint32_t mbar_b  = smem_b + 32768 + warp * 16;

    if (bid < 2 * nbGemm) {
        int half = bid >> 1;
        if ((bid & 1) == 0) {
            gemm_block(half, tei, E, bi, bj, smem);
        } else {
            pack_warp_tma(adj, (size_t)half * 8 + warp, lane, stage_b, mbar_b);
        }
    } else if (bid < 2 * nbGemm + nbS2) {
        int node = (bid - 2 * nbGemm) * 8 + warp;
        if (node < N) {
            float d = warp_dot256(x + (size_t)node * H, g_ws2, lane);
            if (!lane) g_s2[node] = d + g_consts[2];
        }
    } else {
        int pb = nbGemm + (bid - 2 * nbGemm - nbS2);
        pack_warp_tma(adj, (size_t)pb * 8 + warp, lane, stage_b, mbar_b);
    }
}

// ---------------- final edge kernel (uint4 bit-row loads, lane-local decode) ----------------
__global__ void __launch_bounds__(256) edge_kernel(const int* __restrict__ tei, int E, int nwords,
                                                   const float* __restrict__ beta_p,
                                                   const int* __restrict__ boolen_p,
                                                   float* __restrict__ out) {
    int gw = (blockIdx.x * blockDim.x + threadIdx.x) >> 5;
    int lane = threadIdx.x & 31;
    if (gw >= E) return;

    int src = tei[gw];
    int dst = tei[E + gw];

    const uint4* ba = (const uint4*)(g_bits + (size_t)src * nwords);
    const uint4* bb = (const uint4*)(g_bits + (size_t)dst * nwords);

    // front-batch all loads: nwords=256 -> 64 uint4 per row -> 2 iters of 32 lanes
    int iters = nwords >> 7;           // 2
    uint4 a4[2], b4[2];
#pragma unroll
    for (int i = 0; i < 2; i++) {
        if (i < iters) {
            a4[i] = ba[lane + (i << 5)];
            b4[i] = bb[lane + (i << 5)];
        }
    }

    float s = 0.f;
#pragma unroll
    for (int i = 0; i < 2; i++) {
        if (i >= iters) break;
        uint32_t m[4] = {a4[i].x & b4[i].x, a4[i].y & b4[i].y,
                         a4[i].z & b4[i].z, a4[i].w & b4[i].w};
#pragma unroll
        for (int c = 0; c < 4; c++) {
            uint32_t a = m[c];
            if (a) {
                int w = (lane + (i << 5)) * 4 + c;
                // decode: chunk = w>>6, half = w&1, L = (w>>1)&31
                int nb = ((w >> 6) << 11) + ((w & 1) << 10) + ((w >> 1) & 31) * 4;
                do {
                    int b = __ffs(a) - 1;
                    a &= a - 1;
                    s += g_s2[nb + ((b >> 2) << 7) + (b & 3)];
                } while (a);
            }
        }
    }
    float S = warp_red(s);

    if (!lane) {
        float beta = beta_p[0];
        float u = g_t0[gw] + g_t1[gw] + beta * (S + g_consts[0]) + g_consts[1];
        bool pos = boolen_p ? (boolen_p[0] != 0) : true;
        float v = pos ? u : -u;
        out[gw] = fmaxf(-v, 0.f) + log1pf(expf(-fabsf(v)));  // softplus(-v)
    }
}

// ---------------- launch ----------------
extern "C" void kernel_launch(void* const* d_in, const int* in_sizes, int n_in,
                              void* d_out, int out_size) {
    const float* x    = (const float*)d_in[0];
    const float* adj  = (const float*)d_in[1];
    const int*   tei  = (const int*)d_in[2];
    const float* Wlin = (const float*)d_in[3];
    const float* blin = (const float*)d_in[4];
    const float* Wcn  = (const float*)d_in[5];
    const float* bcn  = (const float*)d_in[6];
    const float* Wi   = (const float*)d_in[7];
    const float* bi   = (const float*)d_in[8];
    const float* Wj   = (const float*)d_in[9];
    const float* bj   = (const float*)d_in[10];
    const float* Wf   = (const float*)d_in[11];
    const float* bf   = (const float*)d_in[12];
    const float* ws   = (const float*)d_in[13];
    const float* bs   = (const float*)d_in[14];
    const float* beta = (const float*)d_in[15];
    const int* boolen = (n_in > 16) ? (const int*)d_in[16] : nullptr;
    float* out = (float*)d_out;

    const int N = in_sizes[0] / H;   // 8192 nodes
    const int E = in_sizes[2] / 2;   // 8192 edges
    const int nwords = N / 32;       // 256 words per adjacency row

    // 1) combo head: x split ∥ W split ∥ flag zero ∥ k0a
    combo_kernel<<<(NMAX * H) / 1024 + H + 32 + 2 * H, 256>>>(x, Wi, Wj, Wcn, Wf, ws);
    // 2) k0b (needs vcn) + flagset (needs zeroed flags) in one launch
    k0b_kernel<<<H + 3 + (2 * E + 255) / 256, 256>>>(Wlin, blin, bcn, bf, ws, bs, tei, 2 * E);
    // 3) fused: TMA-staged pack (DRAM) + tensor GEMM + s2 GEMV
    {
        int nbGemm = (E / 64) * 2;                        // 256
        int nbS2   = N / 8;                               // 1024
        int nbPack = (int)((long long)N * N / 2048 / 8);  // 4096
        int total = nbGemm + nbS2 + nbPack;               // 5376
        fused_kernel<<<total, 256>>>(x, adj, tei, bi, bj, N, E);
    }
    // 4) per-edge: CN bit-AND gather + combine + softplus
    edge_kernel<<<(E + 7) / 8, 256>>>(tei, E, nwords, beta, boolen, out);
}

// round 10
// speedup vs baseline: 1.2171x; 1.1856x over previous
#include <cuda_runtime.h>
#include <cuda_bf16.h>
#include <cstdint>

// Problem constants (fixed by the dataset)
#define H    256
#define NMAX 8192
#define EMAX 8192
#define KTOT 512            // concatenated K dim: [xi | xj]

// ---------------- scratch (static __device__ — no allocations) ----------------
__device__ uint32_t      g_bits[(size_t)NMAX * (NMAX / 32)];  // 8 MB packed adjacency (lane-local layout)
__device__ __nv_bfloat16 g_Wthi[(size_t)H * KTOT];            // 256 KB: Wt[n][k] hi
__device__ __nv_bfloat16 g_Wtlo[(size_t)H * KTOT];            // 256 KB
__device__ float         g_t0[EMAX];                          // per-edge relu-dot, cols 0-127
__device__ float         g_t1[EMAX];                          // per-edge relu-dot, cols 128-255
__device__ float         g_s2[NMAX];                          // s2[n] = x2[n]·vcn
__device__ float         g_vcn[H];
__device__ float         g_vf[H];
__device__ float         g_ws2[H];
__device__ float         g_consts[4];                         // [0]=bcn·ws, [1]=bf·ws+bs, [2]=blin·vcn
__device__ unsigned char g_flag[NMAX];                        // adj row referenced by any edge?

// Bit layout (pack/decode contract):
//   chunk gw covers 2048 floats at adj + gw*2048 (4 chunks per adjacency row).
//   lane L, iter i (0..15) packs float4 at float-offset i*128 + L*4 into nibble i.
//   word = g_bits[gw*64 + L*2 + half], half = i>>3, bit b = (i&7)*4 + component j.
//   decode: node = gw*2048 + half*1024 + (b>>2)*128 + L*4 + (b&3).

// ---------------- helpers ----------------
__device__ __forceinline__ float warp_red(float v) {
#pragma unroll
    for (int o = 16; o; o >>= 1) v += __shfl_xor_sync(0xffffffffu, v, o);
    return v;
}

__device__ __forceinline__ float warp_dot256(const float* __restrict__ row,
                                             const float* __restrict__ vec, int lane) {
    float s = 0.f;
#pragma unroll
    for (int c = 0; c < H; c += 32) s = fmaf(row[c + lane], vec[c + lane], s);
    return warp_red(s);
}

// block-wide sum of one float per thread (256 threads); result valid in thread 0
__device__ __forceinline__ float block_red256(float v, float* sm8) {
    int lane = threadIdx.x & 31, w = threadIdx.x >> 5;
    v = warp_red(v);
    if (!lane) sm8[w] = v;
    __syncthreads();
    float t = 0.f;
    if (w == 0) {
        t = (lane < 8) ? sm8[lane] : 0.f;
        t += __shfl_xor_sync(0xffffffffu, t, 1);
        t += __shfl_xor_sync(0xffffffffu, t, 2);
        t += __shfl_xor_sync(0xffffffffu, t, 4);
    }
    return t;
}

__device__ __forceinline__ void mma16816(float c[4], const uint32_t a[4],
                                         uint32_t b0, uint32_t b1) {
    asm volatile(
        "mma.sync.aligned.m16n8k16.row.col.f32.bf16.bf16.f32 "
        "{%0,%1,%2,%3}, {%4,%5,%6,%7}, {%8,%9}, {%0,%1,%2,%3};"
        : "+f"(c[0]), "+f"(c[1]), "+f"(c[2]), "+f"(c[3])
        : "r"(a[0]), "r"(a[1]), "r"(a[2]), "r"(a[3]), "r"(b0), "r"(b1));
}

__device__ __forceinline__ void ldsm4(uint32_t r[4], uint32_t addr) {
    asm volatile("ldmatrix.sync.aligned.m8n8.x4.shared.b16 {%0,%1,%2,%3}, [%4];"
        : "=r"(r[0]), "=r"(r[1]), "=r"(r[2]), "=r"(r[3]) : "r"(addr));
}

// ---------------- combo head kernel: prep-W ∥ flag-zero ∥ k0a ----------------
__global__ void __launch_bounds__(256) combo_kernel(const float* __restrict__ Wi,
                                                    const float* __restrict__ Wj,
                                                    const float* __restrict__ Wcn,
                                                    const float* __restrict__ Wf,
                                                    const float* __restrict__ ws) {
    __shared__ float sm8[8];
    int bid = blockIdx.x;
    int tid = threadIdx.x;
    if (bid < H) {                              // 256 blocks: W transpose+split
        int n = bid;
        for (int k = tid; k < KTOT; k += 256) {
            float w = (k < H) ? Wi[(size_t)k * H + n] : Wj[(size_t)(k - H) * H + n];
            __nv_bfloat16 hi = __float2bfloat16(w);
            __nv_bfloat16 lo = __float2bfloat16(w - __bfloat162float(hi));
            g_Wthi[(size_t)n * KTOT + k] = hi;
            g_Wtlo[(size_t)n * KTOT + k] = lo;
        }
    } else if (bid < H + 32) {                  // 32 blocks: flag zero
        g_flag[(bid - H) * 256 + tid] = 0;
    } else {                                    // 512 blocks: k0a rows
        int r = bid - H - 32;                   // 0..511
        const float* W = (r < H) ? (Wcn + (size_t)r * H) : (Wf + (size_t)(r - H) * H);
        float d = block_red256(W[tid] * ws[tid], sm8);
        if (tid == 0) {
            if (r < H) g_vcn[r] = d;
            else       g_vf[r - H] = d;
        }
    }
}

// ---------------- k0b + flagset: ws2/consts + edge-endpoint flags ----------------
__global__ void __launch_bounds__(256) k0b_kernel(const float* __restrict__ Wlin,
                                                  const float* __restrict__ blin,
                                                  const float* __restrict__ bcn,
                                                  const float* __restrict__ bf,
                                                  const float* __restrict__ ws,
                                                  const float* __restrict__ bs,
                                                  const int* __restrict__ tei, int twoE) {
    __shared__ float sm8[8];
    int b = blockIdx.x;
    int tid = threadIdx.x;
    if (b < H) {
        float d = block_red256(Wlin[(size_t)b * H + tid] * g_vcn[tid], sm8);
        if (tid == 0) g_ws2[b] = g_vcn[b] + d;
    } else if (b == H) {
        float d = block_red256(blin[tid] * g_vcn[tid], sm8);
        if (tid == 0) g_consts[2] = d;
    } else if (b == H + 1) {
        float d = block_red256(bcn[tid] * ws[tid], sm8);
        if (tid == 0) g_consts[0] = d;
    } else if (b == H + 2) {
        float d = block_red256(bf[tid] * ws[tid], sm8);
        if (tid == 0) g_consts[1] = d + bs[0];
    } else {
        int gid = (b - H - 3) * 256 + tid;
        if (gid < twoE) g_flag[tei[gid]] = 1;
    }
}

// ---------------- pack: lane-local, shfl-free, 16 front-batched LDG.128 (R7) ----------------
__device__ __forceinline__ void pack_warp(const float* __restrict__ adj,
                                          size_t gw, int lane) {
    if (!g_flag[gw >> 2]) return;                 // adj row never referenced
    const float4* base = (const float4*)(adj + gw * 2048);
    float4 v[16];
#pragma unroll
    for (int i = 0; i < 16; i++)
        v[i] = __ldcs(base + (size_t)i * 32 + lane);
    uint32_t w0 = 0, w1 = 0;
#pragma unroll
    for (int i = 0; i < 8; i++) {
        uint32_t nib = (uint32_t)(v[i].x != 0.f)
                     | ((uint32_t)(v[i].y != 0.f) << 1)
                     | ((uint32_t)(v[i].z != 0.f) << 2)
                     | ((uint32_t)(v[i].w != 0.f) << 3);
        w0 |= nib << (i * 4);
    }
#pragma unroll
    for (int i = 0; i < 8; i++) {
        uint32_t nib = (uint32_t)(v[8 + i].x != 0.f)
                     | ((uint32_t)(v[8 + i].y != 0.f) << 1)
                     | ((uint32_t)(v[8 + i].z != 0.f) << 2)
                     | ((uint32_t)(v[8 + i].w != 0.f) << 3);
        w1 |= nib << (i * 4);
    }
    ((uint2*)(g_bits + gw * 64))[lane] = make_uint2(w0, w1);
}

// ---------------- tensor-core edge GEMM body: 64 edges x 128 cols, K=512 ----------------
// A-tile gathered directly from fp32 x (L2-resident), hi/lo split in-register.
#define ROWPAD 12
__device__ __forceinline__ void gemm_block(int h, const float* __restrict__ X,
                                           const int* __restrict__ tei, int E,
                                           const float* __restrict__ bi,
                                           const float* __restrict__ bj,
                                           uint32_t* smem) {
    uint32_t* AsHi = smem;                   // 64*12
    uint32_t* AsLo = smem + 768;
    uint32_t* BsHi = smem + 1536;            // 128*12
    uint32_t* BsLo = smem + 3072;
    float*    tsum = (float*)(smem + 4608);  // [2][64]
    int*      eidx = (int*)(smem + 4736);    // [64 src][64 dst]

    int np = h & 1;                          // column half
    int eb = h >> 1;                         // edge tile
    int ebase = eb * 64;

    int tid = threadIdx.x;
    int lane = tid & 31, wid = tid >> 5;
    int wm = wid & 3, wn = wid >> 2;

    if (tid < 64) {
        eidx[tid]      = tei[ebase + tid];
        eidx[64 + tid] = tei[E + ebase + tid];
    }
    __syncthreads();

    int arow = tid >> 2, aq = tid & 3;
    int brow = tid >> 1, bh2 = tid & 1;

    uint32_t asHiB = (uint32_t)__cvta_generic_to_shared(AsHi);
    uint32_t asLoB = (uint32_t)__cvta_generic_to_shared(AsLo);
    uint32_t bsHiB = (uint32_t)__cvta_generic_to_shared(BsHi);
    uint32_t bsLoB = (uint32_t)__cvta_generic_to_shared(BsLo);
    uint32_t aoff = (uint32_t)((wm * 16 + (lane & 15)) * 48 + (lane >> 4) * 16);
    uint32_t boff[4];
#pragma unroll
    for (int jj = 0; jj < 4; jj++)
        boff[jj] = (uint32_t)((wn * 64 + jj * 16 + (lane & 15)) * 48 + (lane >> 4) * 16);

    float acc[8][4];
#pragma unroll
    for (int j = 0; j < 8; j++)
#pragma unroll
        for (int q = 0; q < 4; q++) acc[j][q] = 0.f;

    for (int ks = 0; ks < KTOT / 16; ks++) {
        int k0 = ks * 16;
        {
            int node = eidx[(k0 < H ? 0 : 64) + arow];
            int gc = (k0 & (H - 1)) + aq * 4;
            float4 v = *(const float4*)(X + (size_t)node * H + gc);
            __nv_bfloat16 h0 = __float2bfloat16(v.x), h1 = __float2bfloat16(v.y);
            __nv_bfloat16 h2 = __float2bfloat16(v.z), h3 = __float2bfloat16(v.w);
            __nv_bfloat16 l0 = __float2bfloat16(v.x - __bfloat162float(h0));
            __nv_bfloat16 l1 = __float2bfloat16(v.y - __bfloat162float(h1));
            __nv_bfloat16 l2 = __float2bfloat16(v.z - __bfloat162float(h2));
            __nv_bfloat16 l3 = __float2bfloat16(v.w - __bfloat162float(h3));
            AsHi[arow * ROWPAD + aq * 2 + 0] =
                ((uint32_t)__bfloat16_as_ushort(h1) << 16) | __bfloat16_as_ushort(h0);
            AsHi[arow * ROWPAD + aq * 2 + 1] =
                ((uint32_t)__bfloat16_as_ushort(h3) << 16) | __bfloat16_as_ushort(h2);
            AsLo[arow * ROWPAD + aq * 2 + 0] =
                ((uint32_t)__bfloat16_as_ushort(l1) << 16) | __bfloat16_as_ushort(l0);
            AsLo[arow * ROWPAD + aq * 2 + 1] =
                ((uint32_t)__bfloat16_as_ushort(l3) << 16) | __bfloat16_as_ushort(l2);
        }
        {
            size_t goff = (size_t)(np * 128 + brow) * KTOT + k0 + bh2 * 8;
            *(uint4*)&BsHi[brow * ROWPAD + bh2 * 4] = *(const uint4*)(g_Wthi + goff);
            *(uint4*)&BsLo[brow * ROWPAD + bh2 * 4] = *(const uint4*)(g_Wtlo + goff);
        }
        __syncthreads();

        uint32_t ah[4], al[4];
        ldsm4(ah, asHiB + aoff);
        ldsm4(al, asLoB + aoff);
#pragma unroll
        for (int jj = 0; jj < 4; jj++) {
            uint32_t bhf[4], blf[4];
            ldsm4(bhf, bsHiB + boff[jj]);
            ldsm4(blf, bsLoB + boff[jj]);
            mma16816(acc[2 * jj],     ah, bhf[0], bhf[2]);
            mma16816(acc[2 * jj],     ah, blf[0], blf[2]);
            mma16816(acc[2 * jj],     al, bhf[0], bhf[2]);
            mma16816(acc[2 * jj + 1], ah, bhf[1], bhf[3]);
            mma16816(acc[2 * jj + 1], ah, blf[1], blf[3]);
            mma16816(acc[2 * jj + 1], al, bhf[1], bhf[3]);
        }
        __syncthreads();
    }

    float tp0 = 0.f, tp1 = 0.f;
#pragma unroll
    for (int j = 0; j < 8; j++) {
        int col = np * 128 + wn * 64 + j * 8 + (lane & 3) * 2;
        float b0 = bi[col] + bj[col];
        float b1 = bi[col + 1] + bj[col + 1];
        float v0 = g_vf[col], v1 = g_vf[col + 1];
        tp0 += fmaxf(acc[j][0] + b0, 0.f) * v0 + fmaxf(acc[j][1] + b1, 0.f) * v1;
        tp1 += fmaxf(acc[j][2] + b0, 0.f) * v0 + fmaxf(acc[j][3] + b1, 0.f) * v1;
    }
    tp0 += __shfl_xor_sync(0xffffffffu, tp0, 1);
    tp0 += __shfl_xor_sync(0xffffffffu, tp0, 2);
    tp1 += __shfl_xor_sync(0xffffffffu, tp1, 1);
    tp1 += __shfl_xor_sync(0xffffffffu, tp1, 2);
    if ((lane & 3) == 0) {
        int r = wm * 16 + (lane >> 2);
        tsum[wn * 64 + r] = tp0;
        tsum[wn * 64 + r + 8] = tp1;
    }
    __syncthreads();
    if (tid < 64) {
        float v = tsum[tid] + tsum[64 + tid];
        if (np == 0) g_t0[ebase + tid] = v;
        else         g_t1[ebase + tid] = v;
    }
}

// ---------------- fused kernel: pack ∪ tensor-GEMM ∪ s2 (R7 structure) ----------------
__global__ void __launch_bounds__(256, 3) fused_kernel(const float* __restrict__ x,
                                                       const float* __restrict__ adj,
                                                       const int* __restrict__ tei,
                                                       const float* __restrict__ bi,
                                                       const float* __restrict__ bj,
                                                       int N, int E) {
    __shared__ uint32_t smem[4864];   // 19 KB (gemm role only)

    const int nbGemm = (E / 64) * 2;  // 256
    const int nbS2   = N / 8;         // 1024
    int bid = blockIdx.x;
    int warp = threadIdx.x >> 5;
    int lane = threadIdx.x & 31;

    if (bid < 2 * nbGemm) {
        int half = bid >> 1;
        if ((bid & 1) == 0) {
            gemm_block(half, x, tei, E, bi, bj, smem);
        } else {
            pack_warp(adj, (size_t)half * 8 + warp, lane);
        }
    } else if (bid < 2 * nbGemm + nbS2) {
        int node = (bid - 2 * nbGemm) * 8 + warp;
        if (node < N) {
            float d = warp_dot256(x + (size_t)node * H, g_ws2, lane);
            if (!lane) g_s2[node] = d + g_consts[2];
        }
    } else {
        int pb = nbGemm + (bid - 2 * nbGemm - nbS2);
        pack_warp(adj, (size_t)pb * 8 + warp, lane);
    }
}

// ---------------- final edge kernel: 2 warps per edge ----------------
// nwords=256 -> 64 uint4 per bit-row: each lane loads exactly ONE uint4 per row.
__global__ void __launch_bounds__(256) edge_kernel(const int* __restrict__ tei, int E, int nwords,
                                                   const float* __restrict__ beta_p,
                                                   const int* __restrict__ boolen_p,
                                                   float* __restrict__ out) {
    __shared__ float sred[8];
    int warp = threadIdx.x >> 5;
    int lane = threadIdx.x & 31;
    int e = blockIdx.x * 4 + (warp >> 1);
    int half = warp & 1;
    bool valid = (e < E);

    float s = 0.f;
    if (valid) {
        int src = tei[e];
        int dst = tei[E + e];
        const uint4* ba = (const uint4*)(g_bits + (size_t)src * nwords);
        const uint4* bb = (const uint4*)(g_bits + (size_t)dst * nwords);
        int idx = half * 32 + lane;          // uint4 index within row (0..63)
        uint4 a4 = ba[idx];
        uint4 b4 = bb[idx];
        uint32_t m[4] = {a4.x & b4.x, a4.y & b4.y, a4.z & b4.z, a4.w & b4.w};
#pragma unroll
        for (int c = 0; c < 4; c++) {
            uint32_t a = m[c];
            if (a) {
                int w = idx * 4 + c;
                // decode: chunk = w>>6, half_bit = w&1, L = (w>>1)&31
                int nb = ((w >> 6) << 11) + ((w & 1) << 10) + ((w >> 1) & 31) * 4;
                do {
                    int b = __ffs(a) - 1;
                    a &= a - 1;
                    s += g_s2[nb + ((b >> 2) << 7) + (b & 3)];
                } while (a);
            }
        }
    }
    s = warp_red(s);
    if (!lane) sred[warp] = s;
    __syncthreads();

    if (valid && half == 0 && !lane) {
        float S = sred[warp] + sred[warp + 1];
        float beta = beta_p[0];
        float u = g_t0[e] + g_t1[e] + beta * (S + g_consts[0]) + g_consts[1];
        bool pos = boolen_p ? (boolen_p[0] != 0) : true;
        float v = pos ? u : -u;
        out[e] = fmaxf(-v, 0.f) + log1pf(expf(-fabsf(v)));  // softplus(-v)
    }
}

// ---------------- launch ----------------
extern "C" void kernel_launch(void* const* d_in, const int* in_sizes, int n_in,
                              void* d_out, int out_size) {
    const float* x    = (const float*)d_in[0];
    const float* adj  = (const float*)d_in[1];
    const int*   tei  = (const int*)d_in[2];
    const float* Wlin = (const float*)d_in[3];
    const float* blin = (const float*)d_in[4];
    const float* Wcn  = (const float*)d_in[5];
    const float* bcn  = (const float*)d_in[6];
    const float* Wi   = (const float*)d_in[7];
    const float* bi   = (const float*)d_in[8];
    const float* Wj   = (const float*)d_in[9];
    const float* bj   = (const float*)d_in[10];
    const float* Wf   = (const float*)d_in[11];
    const float* bf   = (const float*)d_in[12];
    const float* ws   = (const float*)d_in[13];
    const float* bs   = (const float*)d_in[14];
    const float* beta = (const float*)d_in[15];
    const int* boolen = (n_in > 16) ? (const int*)d_in[16] : nullptr;
    float* out = (float*)d_out;

    const int N = in_sizes[0] / H;   // 8192 nodes
    const int E = in_sizes[2] / 2;   // 8192 edges
    const int nwords = N / 32;       // 256 words per adjacency row

    // 1) combo head: W split ∥ flag zero ∥ k0a  (x pre-split removed entirely)
    combo_kernel<<<H + 32 + 2 * H, 256>>>(Wi, Wj, Wcn, Wf, ws);
    // 2) k0b (needs vcn) + flagset (needs zeroed flags) in one launch
    k0b_kernel<<<H + 3 + (2 * E + 255) / 256, 256>>>(Wlin, blin, bcn, bf, ws, bs, tei, 2 * E);
    // 3) fused: R7 pack (16-deep LDG.128) + tensor GEMM (direct-x gather) + s2 GEMV
    {
        int nbGemm = (E / 64) * 2;                        // 256
        int nbS2   = N / 8;                               // 1024
        int nbPack = (int)((long long)N * N / 2048 / 8);  // 4096
        int total = nbGemm + nbS2 + nbPack;               // 5376
        fused_kernel<<<total, 256>>>(x, adj, tei, bi, bj, N, E);
    }
    // 4) per-edge: CN bit-AND gather (2 warps/edge) + combine + softplus
    edge_kernel<<<(E + 3) / 4, 256>>>(tei, E, nwords, beta, boolen, out);
}